// round 17
// baseline (speedup 1.0000x reference)
#include <cuda_runtime.h>

#define B_ROWS 8192
#define P_ROWS 1024
#define D_DIM  256
#define NPART  64          // producer blocks, 16 proto rows each
#define NCTR   4           // split arrival counters (different L2 lines)
#define GRID   512         // 256 thr, 4/SM resident -> barrier-safe
#define ROWS_PER_BLK (B_ROWS / GRID)   // 16: 8 warps * 2 rows

// Device-global scratch (allocation-free rule), zero-initialized at load.
__device__ float g_partial[NPART * D_DIM];      // per-producer column sums
__device__ float g_p2[NPART];                   // per-producer sum of squares
__device__ unsigned int g_count[NCTR * 32];     // 4 counters, 128B apart
__device__ unsigned int g_done = 0;             // exit counter (replay reset)

__device__ __forceinline__ unsigned int ld_acq_u32(const unsigned int* p) {
    unsigned int v;
    asm volatile("ld.acquire.gpu.global.u32 %0, [%1];" : "=r"(v) : "l"(p) : "memory");
    return v;
}

__global__ void __launch_bounds__(256, 4)
som_fused(const float* __restrict__ x,
          const float* __restrict__ proto,
          float* __restrict__ out) {
    const int tid  = threadIdx.x;
    const int lane = tid & 31;
    const int warp = tid >> 5;
    const int blk  = blockIdx.x;

    __shared__ __align__(16) float sm_grp[4 * D_DIM];  // row-group partials
    __shared__ __align__(16) float sm_m2[D_DIM];       // combined 2*mean vector
    __shared__ float sm_p2g[8];
    __shared__ float sm_c;

    // x addressing: lane L holds d[4L,4L+4) and d[128+4L,...) of rows row0,row0+1
    // -> every LDG.128 is a fully coalesced 512B warp op.
    const int row0 = blk * ROWS_PER_BLK + warp * 2;
    const float* r0p = x + row0 * D_DIM + lane * 4;
    const float* r1p = r0p + D_DIM;
    float4 a0, a1, b0, b1;

    if (blk < NPART) {
        // ---- Producer: proto loads FIRST (critical path to the barrier) ------
        const int c4   = tid & 63;           // float4 column group
        const int g    = tid >> 6;           // 4 row-groups of 4 rows
        const int prow = blk * (P_ROWS / NPART) + g * 4;

        float4 s = make_float4(0.f, 0.f, 0.f, 0.f);
        float sq = 0.f;
#pragma unroll
        for (int r = 0; r < 4; ++r) {        // 4 independent LDG.128
            float4 v = *reinterpret_cast<const float4*>(
                proto + (prow + r) * D_DIM + c4 * 4);
            s.x += v.x; s.y += v.y; s.z += v.z; s.w += v.w;
            sq  += v.x * v.x + v.y * v.y + v.z * v.z + v.w * v.w;
        }
        *reinterpret_cast<float4*>(&sm_grp[g * D_DIM + c4 * 4]) = s;

#pragma unroll
        for (int o = 16; o > 0; o >>= 1)
            sq += __shfl_down_sync(0xFFFFFFFFu, sq, o);
        if (lane == 0) sm_p2g[warp] = sq;
        __syncthreads();

        g_partial[blk * D_DIM + tid] =
            sm_grp[tid] + sm_grp[D_DIM + tid] +
            sm_grp[2 * D_DIM + tid] + sm_grp[3 * D_DIM + tid];
        if (tid == 0) {
            float p2 = 0.f;
#pragma unroll
            for (int i = 0; i < 8; ++i) p2 += sm_p2g[i];
            g_p2[blk] = p2;
        }

        // R6 race fix: EVERY thread fences its own global store, then arrive
        // on one of 4 L2 lines (16-deep serialization instead of 64-deep).
        __threadfence();
        __syncthreads();
        if (tid == 0)
            atomicAdd(&g_count[(blk & (NCTR - 1)) * 32], 1u);

        // x loads after arrival: latency hides under the spin below.
        a0 = *reinterpret_cast<const float4*>(r0p);
        a1 = *reinterpret_cast<const float4*>(r0p + 128);
        b0 = *reinterpret_cast<const float4*>(r1p);
        b1 = *reinterpret_cast<const float4*>(r1p + 128);
    } else {
        // ---- Consumer: x loads are the FIRST memory ops (R14 win) ------------
        a0 = *reinterpret_cast<const float4*>(r0p);
        a1 = *reinterpret_cast<const float4*>(r0p + 128);
        b0 = *reinterpret_cast<const float4*>(r1p);
        b1 = *reinterpret_cast<const float4*>(r1p + 128);
    }

    // ---- Pre-barrier: Sigma x^2 half of the result + its reduce --------------
    // (no proto dependency; executes in the shadow of the barrier spin.
    //  R12 tested this WITH broken producer ordering -- this isolates it.)
    float sq0 = a0.x * a0.x + a0.y * a0.y + a0.z * a0.z + a0.w * a0.w
              + a1.x * a1.x + a1.y * a1.y + a1.z * a1.z + a1.w * a1.w;
    float sq1 = b0.x * b0.x + b0.y * b0.y + b0.z * b0.z + b0.w * b0.w
              + b1.x * b1.x + b1.y * b1.y + b1.z * b1.z + b1.w * b1.w;
#pragma unroll
    for (int o = 16; o > 0; o >>= 1) {
        sq0 += __shfl_down_sync(0xFFFFFFFFu, sq0, o);
        sq1 += __shfl_down_sync(0xFFFFFFFFu, sq1, o);
    }

    // ---- Grid barrier: spin on the SUM of the 4 counters (MLP=4 per iter) ----
    if (tid == 0) {
        for (;;) {
            unsigned int s = ld_acq_u32(&g_count[0])
                           + ld_acq_u32(&g_count[32])
                           + ld_acq_u32(&g_count[64])
                           + ld_acq_u32(&g_count[96]);
            if (s >= NPART) break;
        }
    }
    __syncthreads();

    // ---- Combine (every block, redundant; L2-resident, proven non-binding) ---
    {
        const int c4 = tid & 63;
        const int g  = tid >> 6;
        float4 s = make_float4(0.f, 0.f, 0.f, 0.f);
#pragma unroll
        for (int i = 0; i < NPART / 4; ++i) {   // 16 partial rows per group
            float4 v = __ldcg(reinterpret_cast<const float4*>(
                &g_partial[(g * (NPART / 4) + i) * D_DIM + c4 * 4]));
            s.x += v.x; s.y += v.y; s.z += v.z; s.w += v.w;
        }
        *reinterpret_cast<float4*>(&sm_grp[g * D_DIM + c4 * 4]) = s;

        if (warp == 0) {                     // all 32 lanes participate (R5 fix)
            float v = __ldcg(&g_p2[lane]) + __ldcg(&g_p2[lane + 32]);
#pragma unroll
            for (int o = 16; o > 0; o >>= 1)
                v += __shfl_down_sync(0xFFFFFFFFu, v, o);
            if (lane == 0) sm_c = v * (1.0f / (float)P_ROWS);
        }
        __syncthreads();

        float m = sm_grp[tid] + sm_grp[D_DIM + tid] +
                  sm_grp[2 * D_DIM + tid] + sm_grp[3 * D_DIM + tid];
        sm_m2[tid] = m * (2.0f / (float)P_ROWS);
        __syncthreads();
    }

    // ---- Post-barrier tail: only the cross term + combine of halves ----------
    const float  c  = sm_c;
    const float4 m0 = *reinterpret_cast<const float4*>(&sm_m2[lane * 4]);
    const float4 m1 = *reinterpret_cast<const float4*>(&sm_m2[128 + lane * 4]);

    float d0 = a0.x * m0.x + a0.y * m0.y + a0.z * m0.z + a0.w * m0.w
             + a1.x * m1.x + a1.y * m1.y + a1.z * m1.z + a1.w * m1.w;
    float d1 = b0.x * m0.x + b0.y * m0.y + b0.z * m0.z + b0.w * m0.w
             + b1.x * m1.x + b1.y * m1.y + b1.z * m1.z + b1.w * m1.w;
#pragma unroll
    for (int o = 16; o > 0; o >>= 1) {
        d0 += __shfl_down_sync(0xFFFFFFFFu, d0, o);
        d1 += __shfl_down_sync(0xFFFFFFFFu, d1, o);
    }
    if (lane == 0) {
        out[row0]     = sq0 - d0 + c;
        out[row0 + 1] = sq1 - d1 + c;
    }

    // ---- Replay-state reset (measured harmless) ------------------------------
    __syncthreads();
    if (tid == 0) {
        unsigned int d = atomicAdd(&g_done, 1u);
        if (d == GRID - 1) {                 // last block out resets everything
            g_count[0]  = 0;
            g_count[32] = 0;
            g_count[64] = 0;
            g_count[96] = 0;
            g_done = 0;
            __threadfence();
        }
    }
}

extern "C" void kernel_launch(void* const* d_in, const int* in_sizes, int n_in,
                              void* d_out, int out_size) {
    const float* x     = (const float*)d_in[0];  // (8192, 256) float32
    const float* proto = (const float*)d_in[1];  // (1024, 256) float32
    float* out = (float*)d_out;                  // (8192,) float32

    som_fused<<<GRID, 256>>>(x, proto, out);
}